// round 8
// baseline (speedup 1.0000x reference)
#include <cuda_runtime.h>
#include <math.h>

#define T_  4
#define C_  512
#define H_  192
#define W_  192
#define HW_ (H_ * W_)
#define CHW_ ((size_t)C_ * HW_)
#define W4_ (W_ / 4)
#define R_  (H_ + 1)    // 193 source-row-pair slots

struct TCoef { float ax, bx, cx, ay, by, cy; };
struct TInt  { int kx, ky; float fx, fy; };

__device__ float g_part[C_ * 4];
__device__ TCoef g_tc[T_];
__device__ TInt  g_ti[T_];
__device__ int   g_fast;
// source-row-sharing fast-path params
__device__ int   g_kyb;          // min_t ky
__device__ int   g_kxb;          // min_t floor(kx/4)
__device__ int   g_delta[T_];    // ky_t - kyb   (0/1)
__device__ int   g_d[T_];        // floor(kx_t/4) - kxb (0/1)
__device__ int   g_s[T_];        // kx_t & 3
__device__ float g_fx[T_], g_fy[T_];

// ---------------------------------------------------------------------------
// Kernel 1: GAP, 4 partial blocks per channel (proven ~14.6us @ 65% DRAM)
// ---------------------------------------------------------------------------
__global__ void gap_kernel(const float* __restrict__ F) {
    int c = blockIdx.x >> 2;
    int q = blockIdx.x & 3;
    const int n4q = HW_ / 16;
    const float4* p = reinterpret_cast<const float4*>(F + (size_t)c * HW_) + q * n4q;
    float s = 0.f;
    #pragma unroll
    for (int i = 0; i < 9; ++i) {
        float4 v = p[i * 256 + threadIdx.x];
        s += (v.x + v.y) + (v.z + v.w);
    }
    #pragma unroll
    for (int o = 16; o > 0; o >>= 1) s += __shfl_xor_sync(0xffffffffu, s, o);
    __shared__ float sh[8];
    if ((threadIdx.x & 31) == 0) sh[threadIdx.x >> 5] = s;
    __syncthreads();
    if (threadIdx.x == 0) {
        float t = 0.f;
        #pragma unroll
        for (int i = 0; i < 8; ++i) t += sh[i];
        g_part[c * 4 + q] = t;
    }
}

// ---------------------------------------------------------------------------
// Kernel 2: theta + fast-path parameter derivation
// ---------------------------------------------------------------------------
__global__ void theta_kernel(const float* __restrict__ w1,
                             const float* __restrict__ b1,
                             const float* __restrict__ a,
                             float* __restrict__ out_tail) {
    int warp = threadIdx.x >> 5;
    int lane = threadIdx.x & 31;

    float s = 0.f;
    for (int k = lane; k < C_; k += 32) {
        float4 pp = *reinterpret_cast<const float4*>(&g_part[4 * k]);
        s += ((pp.x + pp.y) + (pp.z + pp.w)) * w1[warp * C_ + k];
    }
    #pragma unroll
    for (int o = 16; o > 0; o >>= 1) s += __shfl_xor_sync(0xffffffffu, s, o);

    __shared__ float Bs[2 * T_];
    if (lane == 0) Bs[warp] = tanhf(s * (1.0f / (float)HW_) + b1[warp]);
    __syncthreads();

    float a00 = a[0], a01 = a[1], a10 = a[2], a11 = a[3];

    if (threadIdx.x < T_) {
        int t = threadIdx.x;
        float bx = Bs[2 * t + 0];
        float by = Bs[2 * t + 1];
        TCoef tc;
        tc.ax = a00;
        tc.bx = a01 * ((float)W_ / (float)H_);
        tc.cx = 0.5f * (a00 - a00 * (float)W_ + a01 * ((float)W_ / (float)H_)
                        - a01 * (float)W_ + bx * (float)W_ + (float)W_ - 1.0f);
        tc.ay = a10 * ((float)H_ / (float)W_);
        tc.by = a11;
        tc.cy = 0.5f * (a10 * ((float)H_ / (float)W_) - a10 * (float)H_ + a11
                        - a11 * (float)H_ + by * (float)H_ + (float)H_ - 1.0f);
        g_tc[t] = tc;

        TInt ti;
        float kxf = floorf(tc.cx), kyf = floorf(tc.cy);
        ti.kx = (int)kxf;  ti.fx = tc.cx - kxf;
        ti.ky = (int)kyf;  ti.fy = tc.cy - kyf;
        g_ti[t] = ti;
    }
    __syncthreads();

    if (threadIdx.x == 0) {
        bool ident = (a00 == 1.0f && a01 == 0.0f && a10 == 0.0f && a11 == 1.0f);
        // derive shared-window params
        int kyb = 0x7fffffff, kxb = 0x7fffffff;
        int f4[T_];
        for (int t = 0; t < T_; ++t) {
            TInt ti = g_ti[t];
            int st = ti.kx & 3;
            f4[t] = (ti.kx - st) >> 2;       // floor(kx/4), exact
            if (ti.ky < kyb) kyb = ti.ky;
            if (f4[t] < kxb) kxb = f4[t];
        }
        bool span_ok = true;
        for (int t = 0; t < T_; ++t) {
            TInt ti = g_ti[t];
            int dl = ti.ky - kyb;
            int dd = f4[t] - kxb;
            if (dl > 1 || dd > 1) span_ok = false;
            g_delta[t] = dl;
            g_d[t]     = dd;
            g_s[t]     = ti.kx & 3;
            g_fx[t]    = ti.fx;
            g_fy[t]    = ti.fy;
        }
        g_kyb = kyb;
        g_kxb = kxb;
        g_fast = (ident && span_ok) ? 1 : 0;
    }

    if (threadIdx.x < T_ * 4) out_tail[threadIdx.x] = a[threadIdx.x & 3];
    if (threadIdx.x < 2 * T_) out_tail[T_ * 4 + threadIdx.x] = Bs[threadIdx.x];
}

// ---------------------------------------------------------------------------
// Kernel 3: source-row-pair sharing. Thread (c, r, w4) loads rows
// (r+kyb, r+kyb+1) in a 3-float4 window ONCE and emits the output float4 for
// all 4 t (output row r - delta_t). Loads/output: 1.5 float4 vs R2's 4.
// ---------------------------------------------------------------------------
__global__ void __launch_bounds__(256) sample_kernel(const float* __restrict__ F,
                                                     float* __restrict__ out) {
    int idx = blockIdx.x * 256 + threadIdx.x;
    int w4 = idx % W4_;                 // consecutive within warp
    int t2 = idx / W4_;
    int r  = t2 % R_;                   // 0..192
    int c  = t2 / R_;
    if (c >= C_) return;
    int w0 = w4 * 4;

    const float* Fc = F + (size_t)c * HW_;
    const float4 z = make_float4(0.f, 0.f, 0.f, 0.f);

    if (g_fast) {
        int y = r + g_kyb;
        bool vy0 = (unsigned)y       < (unsigned)H_;
        bool vy1 = (unsigned)(y + 1) < (unsigned)H_;
        int base4 = w4 + g_kxb;
        bool interior = (base4 >= 0) && (base4 + 2 < W4_);

        const float4* r0p = reinterpret_cast<const float4*>(
            Fc + (size_t)(vy0 ? y : 0) * W_);
        const float4* r1p = reinterpret_cast<const float4*>(
            Fc + (size_t)(vy1 ? (y + 1) : 0) * W_);

        float4 P0, P1, P2, Q0, Q1, Q2;
        if (interior) {
            P0 = __ldg(&r0p[base4]); P1 = __ldg(&r0p[base4 + 1]); P2 = __ldg(&r0p[base4 + 2]);
            Q0 = __ldg(&r1p[base4]); Q1 = __ldg(&r1p[base4 + 1]); Q2 = __ldg(&r1p[base4 + 2]);
        } else {
            int b0 = min(max(base4,     0), W4_ - 1);
            int b1 = min(max(base4 + 1, 0), W4_ - 1);
            int b2 = min(max(base4 + 2, 0), W4_ - 1);
            P0 = __ldg(&r0p[b0]); P1 = __ldg(&r0p[b1]); P2 = __ldg(&r0p[b2]);
            Q0 = __ldg(&r1p[b0]); Q1 = __ldg(&r1p[b1]); Q2 = __ldg(&r1p[b2]);
        }
        if (!vy0) { P0 = z; P1 = z; P2 = z; }
        if (!vy1) { Q0 = z; Q1 = z; Q2 = z; }

        #pragma unroll
        for (int t = 0; t < T_; ++t) {
            int o_row = r - g_delta[t];
            if ((unsigned)o_row >= (unsigned)H_) continue;
            int   d  = g_d[t];
            float fy = g_fy[t];
            float fx = g_fx[t];

            float4 Pa = d ? P1 : P0;
            float4 Pb = d ? P2 : P1;
            float4 Qa = d ? Q1 : Q0;
            float4 Qb = d ? Q2 : Q1;

            float m0 = Pa.x + fy * (Qa.x - Pa.x);
            float m1 = Pa.y + fy * (Qa.y - Pa.y);
            float m2 = Pa.z + fy * (Qa.z - Pa.z);
            float m3 = Pa.w + fy * (Qa.w - Pa.w);
            float m4 = Pb.x + fy * (Qb.x - Pb.x);
            float m5 = Pb.y + fy * (Qb.y - Pb.y);
            float m6 = Pb.z + fy * (Qb.z - Pb.z);
            float m7 = Pb.w + fy * (Qb.w - Pb.w);

            if (!interior) {
                int xb = 4 * (base4 + d);   // true col of m0
                if ((unsigned)(xb + 0) >= (unsigned)W_) m0 = 0.f;
                if ((unsigned)(xb + 1) >= (unsigned)W_) m1 = 0.f;
                if ((unsigned)(xb + 2) >= (unsigned)W_) m2 = 0.f;
                if ((unsigned)(xb + 3) >= (unsigned)W_) m3 = 0.f;
                if ((unsigned)(xb + 4) >= (unsigned)W_) m4 = 0.f;
                if ((unsigned)(xb + 5) >= (unsigned)W_) m5 = 0.f;
                if ((unsigned)(xb + 6) >= (unsigned)W_) m6 = 0.f;
                if ((unsigned)(xb + 7) >= (unsigned)W_) m7 = 0.f;
            }

            float4 o;
            #define MIX_(e0, e1) ((e0) + fx * ((e1) - (e0)))
            switch (g_s[t]) {   // uniform branch
                case 0: o.x=MIX_(m0,m1); o.y=MIX_(m1,m2); o.z=MIX_(m2,m3); o.w=MIX_(m3,m4); break;
                case 1: o.x=MIX_(m1,m2); o.y=MIX_(m2,m3); o.z=MIX_(m3,m4); o.w=MIX_(m4,m5); break;
                case 2: o.x=MIX_(m2,m3); o.y=MIX_(m3,m4); o.z=MIX_(m4,m5); o.w=MIX_(m5,m6); break;
                default:o.x=MIX_(m3,m4); o.y=MIX_(m4,m5); o.z=MIX_(m5,m6); o.w=MIX_(m6,m7); break;
            }
            #undef MIX_
            __stcs(reinterpret_cast<float4*>(
                out + (size_t)t * CHW_ + (size_t)c * HW_ + (size_t)o_row * W_ + w0), o);
        }
    } else {
        // General affine fallback: one output row (r) if valid, scalar gathers
        if (r >= H_) return;
        int h = r;
        float* outp = out + (size_t)c * HW_ + (size_t)h * W_ + w0;
        #pragma unroll
        for (int t = 0; t < T_; ++t) {
            TCoef tc = g_tc[t];
            float bases_x = tc.bx * (float)h + tc.cx;
            float bases_y = tc.by * (float)h + tc.cy;
            float4 o;
            float* op = reinterpret_cast<float*>(&o);
            #pragma unroll
            for (int j = 0; j < 4; ++j) {
                float wf = (float)(w0 + j);
                float ix = tc.ax * wf + bases_x;
                float iy = tc.ay * wf + bases_y;
                float ix0f = floorf(ix), iy0f = floorf(iy);
                float fx = ix - ix0f,   fy = iy - iy0f;
                int x0 = (int)ix0f, y0 = (int)iy0f;
                int x1 = x0 + 1,    y1 = y0 + 1;
                bool vx0 = (unsigned)x0 < (unsigned)W_;
                bool vx1 = (unsigned)x1 < (unsigned)W_;
                bool vy0 = (unsigned)y0 < (unsigned)H_;
                bool vy1 = (unsigned)y1 < (unsigned)H_;
                const float* r0 = Fc + (size_t)(vy0 ? y0 : 0) * W_;
                const float* r1 = Fc + (size_t)(vy1 ? y1 : 0) * W_;
                float v00 = (vy0 && vx0) ? __ldg(r0 + x0) : 0.f;
                float v01 = (vy0 && vx1) ? __ldg(r0 + x1) : 0.f;
                float v10 = (vy1 && vx0) ? __ldg(r1 + x0) : 0.f;
                float v11 = (vy1 && vx1) ? __ldg(r1 + x1) : 0.f;
                float wx0 = 1.f - fx, wx1 = fx;
                float wy0 = 1.f - fy, wy1 = fy;
                op[j] = wy0 * (wx0 * v00 + wx1 * v01) + wy1 * (wx0 * v10 + wx1 * v11);
            }
            __stcs(reinterpret_cast<float4*>(outp + (size_t)t * CHW_), o);
        }
    }
}

// ---------------------------------------------------------------------------
extern "C" void kernel_launch(void* const* d_in, const int* in_sizes, int n_in,
                              void* d_out, int out_size) {
    const float* F  = (const float*)d_in[0];
    const float* w1 = (const float*)d_in[1];
    const float* b1 = (const float*)d_in[2];
    const float* a  = (const float*)d_in[3];
    float* out = (float*)d_out;

    float* out_tail = out + (size_t)T_ * CHW_;

    gap_kernel<<<C_ * 4, 256>>>(F);
    theta_kernel<<<1, 256>>>(w1, b1, a, out_tail);

    const int total = C_ * R_ * W4_;     // 512*193*48 = 4,743,168
    sample_kernel<<<(total + 255) / 256, 256>>>(F, out);
}

// round 9
// speedup vs baseline: 1.0556x; 1.0556x over previous
#include <cuda_runtime.h>
#include <math.h>

#define T_  4
#define C_  512
#define H_  192
#define W_  192
#define HW_ (H_ * W_)
#define CHW_ ((size_t)C_ * HW_)
#define W4_ (W_ / 4)
#define HB_ (H_ / 8)           // 24 row-blocks per channel
#define TROWS_ 10              // source rows per tile
#define TCOLS_ 50              // source float4 cols per tile
#define TSTRIDE_ 52            // padded row stride in float4

struct TCoef { float ax, bx, cx, ay, by, cy; };
struct TInt  { int kx, ky; float fx, fy; };

__device__ float g_part[C_ * 4];
__device__ TCoef g_tc[T_];
__device__ TInt  g_ti[T_];
__device__ int   g_fast;
__device__ int   g_kyb;          // min_t ky
__device__ int   g_kxb;          // min_t floor(kx/4)
__device__ int   g_delta[T_];    // ky_t - kyb   (0/1)
__device__ int   g_d[T_];        // floor(kx_t/4) - kxb (0/1)
__device__ int   g_s[T_];        // kx_t & 3
__device__ float g_fx[T_], g_fy[T_];

// ---------------------------------------------------------------------------
// Kernel 1: GAP, 4 partial blocks per channel (proven ~14.6us @ 65% DRAM)
// ---------------------------------------------------------------------------
__global__ void gap_kernel(const float* __restrict__ F) {
    int c = blockIdx.x >> 2;
    int q = blockIdx.x & 3;
    const int n4q = HW_ / 16;
    const float4* p = reinterpret_cast<const float4*>(F + (size_t)c * HW_) + q * n4q;
    float s = 0.f;
    #pragma unroll
    for (int i = 0; i < 9; ++i) {
        float4 v = p[i * 256 + threadIdx.x];
        s += (v.x + v.y) + (v.z + v.w);
    }
    #pragma unroll
    for (int o = 16; o > 0; o >>= 1) s += __shfl_xor_sync(0xffffffffu, s, o);
    __shared__ float sh[8];
    if ((threadIdx.x & 31) == 0) sh[threadIdx.x >> 5] = s;
    __syncthreads();
    if (threadIdx.x == 0) {
        float t = 0.f;
        #pragma unroll
        for (int i = 0; i < 8; ++i) t += sh[i];
        g_part[c * 4 + q] = t;
    }
}

// ---------------------------------------------------------------------------
// Kernel 2: theta + fast-path parameter derivation
// ---------------------------------------------------------------------------
__global__ void theta_kernel(const float* __restrict__ w1,
                             const float* __restrict__ b1,
                             const float* __restrict__ a,
                             float* __restrict__ out_tail) {
    int warp = threadIdx.x >> 5;
    int lane = threadIdx.x & 31;

    float s = 0.f;
    for (int k = lane; k < C_; k += 32) {
        float4 pp = *reinterpret_cast<const float4*>(&g_part[4 * k]);
        s += ((pp.x + pp.y) + (pp.z + pp.w)) * w1[warp * C_ + k];
    }
    #pragma unroll
    for (int o = 16; o > 0; o >>= 1) s += __shfl_xor_sync(0xffffffffu, s, o);

    __shared__ float Bs[2 * T_];
    if (lane == 0) Bs[warp] = tanhf(s * (1.0f / (float)HW_) + b1[warp]);
    __syncthreads();

    float a00 = a[0], a01 = a[1], a10 = a[2], a11 = a[3];

    if (threadIdx.x < T_) {
        int t = threadIdx.x;
        float bx = Bs[2 * t + 0];
        float by = Bs[2 * t + 1];
        TCoef tc;
        tc.ax = a00;
        tc.bx = a01 * ((float)W_ / (float)H_);
        tc.cx = 0.5f * (a00 - a00 * (float)W_ + a01 * ((float)W_ / (float)H_)
                        - a01 * (float)W_ + bx * (float)W_ + (float)W_ - 1.0f);
        tc.ay = a10 * ((float)H_ / (float)W_);
        tc.by = a11;
        tc.cy = 0.5f * (a10 * ((float)H_ / (float)W_) - a10 * (float)H_ + a11
                        - a11 * (float)H_ + by * (float)H_ + (float)H_ - 1.0f);
        g_tc[t] = tc;

        TInt ti;
        float kxf = floorf(tc.cx), kyf = floorf(tc.cy);
        ti.kx = (int)kxf;  ti.fx = tc.cx - kxf;
        ti.ky = (int)kyf;  ti.fy = tc.cy - kyf;
        g_ti[t] = ti;
    }
    __syncthreads();

    if (threadIdx.x == 0) {
        bool ident = (a00 == 1.0f && a01 == 0.0f && a10 == 0.0f && a11 == 1.0f);
        int kyb = 0x7fffffff, kxb = 0x7fffffff;
        int f4[T_];
        for (int t = 0; t < T_; ++t) {
            TInt ti = g_ti[t];
            int st = ti.kx & 3;
            f4[t] = (ti.kx - st) >> 2;
            if (ti.ky < kyb) kyb = ti.ky;
            if (f4[t] < kxb) kxb = f4[t];
        }
        bool span_ok = true;
        for (int t = 0; t < T_; ++t) {
            TInt ti = g_ti[t];
            int dl = ti.ky - kyb;
            int dd = f4[t] - kxb;
            if (dl > 1 || dd > 1) span_ok = false;
            g_delta[t] = dl;
            g_d[t]     = dd;
            g_s[t]     = ti.kx & 3;
            g_fx[t]    = ti.fx;
            g_fy[t]    = ti.fy;
        }
        g_kyb = kyb;
        g_kxb = kxb;
        g_fast = (ident && span_ok) ? 1 : 0;
    }

    if (threadIdx.x < T_ * 4) out_tail[threadIdx.x] = a[threadIdx.x & 3];
    if (threadIdx.x < 2 * T_) out_tail[T_ * 4 + threadIdx.x] = Bs[threadIdx.x];
}

// ---------------------------------------------------------------------------
// Kernel 3: SMEM-tiled bilinear warp. Block = (channel, 8 output rows).
// Stage 10 src rows x 50 float4 (zero-filled OOB) once; emit 8x48 float4
// for all 4 t from SMEM. No masks/clamps in compute. F read ~once from L2.
// ---------------------------------------------------------------------------
__global__ void __launch_bounds__(256) sample_kernel(const float* __restrict__ F,
                                                     float* __restrict__ out) {
    __shared__ float4 S[TROWS_][TSTRIDE_];

    int c  = blockIdx.x / HB_;
    int hb = blockIdx.x - c * HB_;
    int h0 = hb * 8;
    int tid = threadIdx.x;

    const float* Fc = F + (size_t)c * HW_;

    if (g_fast) {
        int kyb = g_kyb, kxb = g_kxb;
        int y_base = h0 + kyb;

        // ---- stage tile (zero-filled out-of-range) ----
        #pragma unroll
        for (int i = tid; i < TROWS_ * TCOLS_; i += 256) {
            int row = i / TCOLS_;
            int col = i - row * TCOLS_;
            int y = y_base + row;
            int g = kxb + col;
            float4 v = make_float4(0.f, 0.f, 0.f, 0.f);
            if ((unsigned)y < (unsigned)H_ && (unsigned)g < (unsigned)W4_)
                v = __ldg(reinterpret_cast<const float4*>(Fc + (size_t)y * W_) + g);
            S[row][col] = v;
        }
        __syncthreads();

        // ---- emit 1536 output float4 (4t x 8rows x 48cols) = 6 per thread ----
        #pragma unroll
        for (int iter = 0; iter < 6; ++iter) {
            int linear = iter * 256 + tid;
            int t   = linear / 384;            // uniform per warp (384 = 12*32)
            int rem = linear - t * 384;
            int j   = rem / 48;
            int w4  = rem - j * 48;

            int   dl = g_delta[t];
            int   dd = g_d[t];
            int   st = g_s[t];
            float fx = g_fx[t];
            float fy = g_fy[t];

            int sr = j + dl;
            int sc = w4 + dd;

            float4 Pa = S[sr][sc];
            float4 Pb = S[sr][sc + 1];
            float4 Qa = S[sr + 1][sc];
            float4 Qb = S[sr + 1][sc + 1];

            float m0 = Pa.x + fy * (Qa.x - Pa.x);
            float m1 = Pa.y + fy * (Qa.y - Pa.y);
            float m2 = Pa.z + fy * (Qa.z - Pa.z);
            float m3 = Pa.w + fy * (Qa.w - Pa.w);
            float m4 = Pb.x + fy * (Qb.x - Pb.x);
            float m5 = Pb.y + fy * (Qb.y - Pb.y);
            float m6 = Pb.z + fy * (Qb.z - Pb.z);
            float m7 = Pb.w + fy * (Qb.w - Pb.w);

            float4 o;
            #define MIX_(e0, e1) ((e0) + fx * ((e1) - (e0)))
            switch (st) {   // uniform per warp
                case 0: o.x=MIX_(m0,m1); o.y=MIX_(m1,m2); o.z=MIX_(m2,m3); o.w=MIX_(m3,m4); break;
                case 1: o.x=MIX_(m1,m2); o.y=MIX_(m2,m3); o.z=MIX_(m3,m4); o.w=MIX_(m4,m5); break;
                case 2: o.x=MIX_(m2,m3); o.y=MIX_(m3,m4); o.z=MIX_(m4,m5); o.w=MIX_(m5,m6); break;
                default:o.x=MIX_(m3,m4); o.y=MIX_(m4,m5); o.z=MIX_(m5,m6); o.w=MIX_(m6,m7); break;
            }
            #undef MIX_
            __stcs(reinterpret_cast<float4*>(
                out + (size_t)t * CHW_ + (size_t)c * HW_
                    + (size_t)(h0 + j) * W_ + 4 * w4), o);
        }
    } else {
        // ---- general affine fallback: same mapping, scalar gathers ----
        #pragma unroll
        for (int iter = 0; iter < 6; ++iter) {
            int linear = iter * 256 + tid;
            int t   = linear / 384;
            int rem = linear - t * 384;
            int j   = rem / 48;
            int w4  = rem - j * 48;
            int h   = h0 + j;
            int w0  = 4 * w4;

            TCoef tc = g_tc[t];
            float bases_x = tc.bx * (float)h + tc.cx;
            float bases_y = tc.by * (float)h + tc.cy;
            float4 o;
            float* op = reinterpret_cast<float*>(&o);
            #pragma unroll
            for (int k = 0; k < 4; ++k) {
                float wf = (float)(w0 + k);
                float ix = tc.ax * wf + bases_x;
                float iy = tc.ay * wf + bases_y;
                float ix0f = floorf(ix), iy0f = floorf(iy);
                float fx = ix - ix0f,   fy = iy - iy0f;
                int x0 = (int)ix0f, y0 = (int)iy0f;
                int x1 = x0 + 1,    y1 = y0 + 1;
                bool vx0 = (unsigned)x0 < (unsigned)W_;
                bool vx1 = (unsigned)x1 < (unsigned)W_;
                bool vy0 = (unsigned)y0 < (unsigned)H_;
                bool vy1 = (unsigned)y1 < (unsigned)H_;
                const float* r0 = Fc + (size_t)(vy0 ? y0 : 0) * W_;
                const float* r1 = Fc + (size_t)(vy1 ? y1 : 0) * W_;
                float v00 = (vy0 && vx0) ? __ldg(r0 + x0) : 0.f;
                float v01 = (vy0 && vx1) ? __ldg(r0 + x1) : 0.f;
                float v10 = (vy1 && vx0) ? __ldg(r1 + x0) : 0.f;
                float v11 = (vy1 && vx1) ? __ldg(r1 + x1) : 0.f;
                float wx0 = 1.f - fx, wx1 = fx;
                float wy0 = 1.f - fy, wy1 = fy;
                op[k] = wy0 * (wx0 * v00 + wx1 * v01) + wy1 * (wx0 * v10 + wx1 * v11);
            }
            __stcs(reinterpret_cast<float4*>(
                out + (size_t)t * CHW_ + (size_t)c * HW_
                    + (size_t)h * W_ + w0), o);
        }
    }
}

// ---------------------------------------------------------------------------
extern "C" void kernel_launch(void* const* d_in, const int* in_sizes, int n_in,
                              void* d_out, int out_size) {
    const float* F  = (const float*)d_in[0];
    const float* w1 = (const float*)d_in[1];
    const float* b1 = (const float*)d_in[2];
    const float* a  = (const float*)d_in[3];
    float* out = (float*)d_out;

    float* out_tail = out + (size_t)T_ * CHW_;

    gap_kernel<<<C_ * 4, 256>>>(F);
    theta_kernel<<<1, 256>>>(w1, b1, a, out_tail);

    sample_kernel<<<C_ * HB_, 256>>>(F, out);   // 12288 blocks
}

// round 10
// speedup vs baseline: 1.1202x; 1.0612x over previous
#include <cuda_runtime.h>
#include <math.h>

#define T_  4
#define C_  512
#define H_  192
#define W_  192
#define HW_ (H_ * W_)
#define CHW_ ((size_t)C_ * HW_)
#define W4_ (W_ / 4)

struct TCoef { float ax, bx, cx, ay, by, cy; };
struct TInt  { int kx, ky; float fx, fy; };

__device__ float g_part[C_ * 4];
__device__ TCoef g_tc[T_];
__device__ TInt  g_ti[T_];
__device__ int   g_fast;

// ---------------------------------------------------------------------------
// Kernel 1: GAP, 4 partial blocks per channel (proven ~14.6us @ 65% DRAM)
// ---------------------------------------------------------------------------
__global__ void gap_kernel(const float* __restrict__ F) {
    int c = blockIdx.x >> 2;
    int q = blockIdx.x & 3;
    const int n4q = HW_ / 16;
    const float4* p = reinterpret_cast<const float4*>(F + (size_t)c * HW_) + q * n4q;
    float s = 0.f;
    #pragma unroll
    for (int i = 0; i < 9; ++i) {
        float4 v = p[i * 256 + threadIdx.x];
        s += (v.x + v.y) + (v.z + v.w);
    }
    #pragma unroll
    for (int o = 16; o > 0; o >>= 1) s += __shfl_xor_sync(0xffffffffu, s, o);
    __shared__ float sh[8];
    if ((threadIdx.x & 31) == 0) sh[threadIdx.x >> 5] = s;
    __syncthreads();
    if (threadIdx.x == 0) {
        float t = 0.f;
        #pragma unroll
        for (int i = 0; i < 8; ++i) t += sh[i];
        g_part[c * 4 + q] = t;
    }
}

// ---------------------------------------------------------------------------
// Kernel 2: theta
// ---------------------------------------------------------------------------
__global__ void theta_kernel(const float* __restrict__ w1,
                             const float* __restrict__ b1,
                             const float* __restrict__ a,
                             float* __restrict__ out_tail) {
    int warp = threadIdx.x >> 5;
    int lane = threadIdx.x & 31;

    float s = 0.f;
    for (int k = lane; k < C_; k += 32) {
        float4 pp = *reinterpret_cast<const float4*>(&g_part[4 * k]);
        s += ((pp.x + pp.y) + (pp.z + pp.w)) * w1[warp * C_ + k];
    }
    #pragma unroll
    for (int o = 16; o > 0; o >>= 1) s += __shfl_xor_sync(0xffffffffu, s, o);

    __shared__ float Bs[2 * T_];
    if (lane == 0) Bs[warp] = tanhf(s * (1.0f / (float)HW_) + b1[warp]);
    __syncthreads();

    float a00 = a[0], a01 = a[1], a10 = a[2], a11 = a[3];

    if (threadIdx.x == 0)
        g_fast = (a00 == 1.0f && a01 == 0.0f && a10 == 0.0f && a11 == 1.0f) ? 1 : 0;

    if (threadIdx.x < T_) {
        int t = threadIdx.x;
        float bx = Bs[2 * t + 0];
        float by = Bs[2 * t + 1];
        TCoef tc;
        tc.ax = a00;
        tc.bx = a01 * ((float)W_ / (float)H_);
        tc.cx = 0.5f * (a00 - a00 * (float)W_ + a01 * ((float)W_ / (float)H_)
                        - a01 * (float)W_ + bx * (float)W_ + (float)W_ - 1.0f);
        tc.ay = a10 * ((float)H_ / (float)W_);
        tc.by = a11;
        tc.cy = 0.5f * (a10 * ((float)H_ / (float)W_) - a10 * (float)H_ + a11
                        - a11 * (float)H_ + by * (float)H_ + (float)H_ - 1.0f);
        g_tc[t] = tc;

        TInt ti;
        float kxf = floorf(tc.cx), kyf = floorf(tc.cy);
        ti.kx = (int)kxf;  ti.fx = tc.cx - kxf;
        ti.ky = (int)kyf;  ti.fy = tc.cy - kyf;
        g_ti[t] = ti;
    }

    if (threadIdx.x < T_ * 4) out_tail[threadIdx.x] = a[threadIdx.x & 3];
    if (threadIdx.x < 2 * T_) out_tail[T_ * 4 + threadIdx.x] = Bs[threadIdx.x];
}

// ---------------------------------------------------------------------------
// Kernel 3: bilinear warp (R6 body). 3D launch removes ALL index math:
// block=(48,8) -> w4=tx, h=bx*8+ty, c=by. Block tiles 8 rows x full width
// of one channel (vertical L1 reuse inside one block's residency).
// ---------------------------------------------------------------------------
__global__ void __launch_bounds__(384) sample_kernel(const float* __restrict__ F,
                                                     float* __restrict__ out) {
    int w4 = threadIdx.x;                    // 0..47
    int h  = blockIdx.x * 8 + threadIdx.y;   // 0..191
    int c  = blockIdx.y;                     // 0..511
    int w0 = w4 * 4;

    const float* Fc = F + (size_t)c * HW_;
    float* outp = out + (size_t)c * HW_ + (size_t)h * W_ + w0;

    if (g_fast) {
        #pragma unroll
        for (int t = 0; t < T_; ++t) {
            TInt ti = g_ti[t];
            int y0 = h + ti.ky;
            bool vy0 = (unsigned)y0 < (unsigned)H_;
            bool vy1 = (unsigned)(y0 + 1) < (unsigned)H_;
            int x0 = w0 + ti.kx;
            int s  = ti.kx & 3;                 // uniform across grid
            int base4 = (x0 - s) >> 2;          // aligned float4 index
            int b0 = min(max(base4, 0), W4_ - 1);
            int b1 = min(max(base4 + 1, 0), W4_ - 1);

            const float4* r0p = reinterpret_cast<const float4*>(
                Fc + (size_t)(vy0 ? y0 : 0) * W_);
            const float4* r1p = reinterpret_cast<const float4*>(
                Fc + (size_t)(vy1 ? (y0 + 1) : 0) * W_);

            float4 A0 = __ldg(&r0p[b0]);
            float4 A1 = __ldg(&r0p[b1]);
            float4 B0 = __ldg(&r1p[b0]);
            float4 B1 = __ldg(&r1p[b1]);
            if (!vy0) { A0 = make_float4(0,0,0,0); A1 = make_float4(0,0,0,0); }
            if (!vy1) { B0 = make_float4(0,0,0,0); B1 = make_float4(0,0,0,0); }

            float fy = ti.fy;
            float m0 = A0.x + fy * (B0.x - A0.x);
            float m1 = A0.y + fy * (B0.y - A0.y);
            float m2 = A0.z + fy * (B0.z - A0.z);
            float m3 = A0.w + fy * (B0.w - A0.w);
            float m4 = A1.x + fy * (B1.x - A1.x);
            float m5 = A1.y + fy * (B1.y - A1.y);
            float m6 = A1.z + fy * (B1.z - A1.z);
            float m7 = A1.w + fy * (B1.w - A1.w);

            int xb = 4 * base4;
            if ((unsigned)(xb + 0) >= (unsigned)W_) m0 = 0.f;
            if ((unsigned)(xb + 1) >= (unsigned)W_) m1 = 0.f;
            if ((unsigned)(xb + 2) >= (unsigned)W_) m2 = 0.f;
            if ((unsigned)(xb + 3) >= (unsigned)W_) m3 = 0.f;
            if ((unsigned)(xb + 4) >= (unsigned)W_) m4 = 0.f;
            if ((unsigned)(xb + 5) >= (unsigned)W_) m5 = 0.f;
            if ((unsigned)(xb + 6) >= (unsigned)W_) m6 = 0.f;
            if ((unsigned)(xb + 7) >= (unsigned)W_) m7 = 0.f;

            float fx = ti.fx;
            float4 o;
            #define MIX_(e0, e1) ((e0) + fx * ((e1) - (e0)))
            switch (s) {   // uniform branch: all warps take the same case
                case 0: o.x=MIX_(m0,m1); o.y=MIX_(m1,m2); o.z=MIX_(m2,m3); o.w=MIX_(m3,m4); break;
                case 1: o.x=MIX_(m1,m2); o.y=MIX_(m2,m3); o.z=MIX_(m3,m4); o.w=MIX_(m4,m5); break;
                case 2: o.x=MIX_(m2,m3); o.y=MIX_(m3,m4); o.z=MIX_(m4,m5); o.w=MIX_(m5,m6); break;
                default:o.x=MIX_(m3,m4); o.y=MIX_(m4,m5); o.z=MIX_(m5,m6); o.w=MIX_(m6,m7); break;
            }
            #undef MIX_
            __stcs(reinterpret_cast<float4*>(outp + (size_t)t * CHW_), o);
        }
    } else {
        // General affine fallback (scalar gathers)
        #pragma unroll
        for (int t = 0; t < T_; ++t) {
            TCoef tc = g_tc[t];
            float bases_x = tc.bx * (float)h + tc.cx;
            float bases_y = tc.by * (float)h + tc.cy;
            float4 o;
            float* op = reinterpret_cast<float*>(&o);
            #pragma unroll
            for (int j = 0; j < 4; ++j) {
                float wf = (float)(w0 + j);
                float ix = tc.ax * wf + bases_x;
                float iy = tc.ay * wf + bases_y;
                float ix0f = floorf(ix), iy0f = floorf(iy);
                float fx = ix - ix0f,   fy = iy - iy0f;
                int x0 = (int)ix0f, y0 = (int)iy0f;
                int x1 = x0 + 1,    y1 = y0 + 1;
                bool vx0 = (unsigned)x0 < (unsigned)W_;
                bool vx1 = (unsigned)x1 < (unsigned)W_;
                bool vy0 = (unsigned)y0 < (unsigned)H_;
                bool vy1 = (unsigned)y1 < (unsigned)H_;
                const float* r0 = Fc + (size_t)(vy0 ? y0 : 0) * W_;
                const float* r1 = Fc + (size_t)(vy1 ? y1 : 0) * W_;
                float v00 = (vy0 && vx0) ? __ldg(r0 + x0) : 0.f;
                float v01 = (vy0 && vx1) ? __ldg(r0 + x1) : 0.f;
                float v10 = (vy1 && vx0) ? __ldg(r1 + x0) : 0.f;
                float v11 = (vy1 && vx1) ? __ldg(r1 + x1) : 0.f;
                float wx0 = 1.f - fx, wx1 = fx;
                float wy0 = 1.f - fy, wy1 = fy;
                op[j] = wy0 * (wx0 * v00 + wx1 * v01) + wy1 * (wx0 * v10 + wx1 * v11);
            }
            __stcs(reinterpret_cast<float4*>(outp + (size_t)t * CHW_), o);
        }
    }
}

// ---------------------------------------------------------------------------
extern "C" void kernel_launch(void* const* d_in, const int* in_sizes, int n_in,
                              void* d_out, int out_size) {
    const float* F  = (const float*)d_in[0];
    const float* w1 = (const float*)d_in[1];
    const float* b1 = (const float*)d_in[2];
    const float* a  = (const float*)d_in[3];
    float* out = (float*)d_out;

    float* out_tail = out + (size_t)T_ * CHW_;

    gap_kernel<<<C_ * 4, 256>>>(F);
    theta_kernel<<<1, 256>>>(w1, b1, a, out_tail);

    dim3 blk(48, 8);              // 384 threads: w4 x 8 rows
    dim3 grd(H_ / 8, C_);         // 24 x 512 blocks
    sample_kernel<<<grd, blk>>>(F, out);
}